// round 16
// baseline (speedup 1.0000x reference)
#include <cuda_runtime.h>
#include <cuda_fp16.h>
#include <cstdint>

#define N_NODES  4096
#define N_EDGES  16384
#define N_GRAPHS 128
#define DIM      64     // IN = H = 64 for all layers
#define EDIM     16
#define HD       4096   // DIM*DIM, edge-MLP width

// ---------------------------------------------------------------------------
// Scratch (static __device__ globals: no allocation anywhere)
// ---------------------------------------------------------------------------
__device__ __half g_h[N_EDGES * HD];      // 134 MB: relu(ea@w1+b1) in fp16
__device__ __half g_w2h[HD * HD];         // 32 MB: w2 transposed [N,K] in fp16
__device__ float  g_feat[2][N_NODES * DIM];
__device__ float  g_agg[N_NODES * DIM];
__device__ float  g_cnt[N_NODES];
__device__ float  g_gcnt[N_GRAPHS];

// ---------------------------------------------------------------------------
// Utility kernels
// ---------------------------------------------------------------------------
__global__ void zero_kernel(float* __restrict__ p, int n) {
    int i = blockIdx.x * blockDim.x + threadIdx.x;
    if (i < n) p[i] = 0.0f;
}

__global__ void cnt_kernel(const int* __restrict__ ei) {
    int e = blockIdx.x * blockDim.x + threadIdx.x;
    if (e < N_EDGES) atomicAdd(&g_cnt[ei[N_EDGES + e]], 1.0f);
}

// w2 [K,N] fp32 -> g_w2h [N,K] fp16 (B operand, K-contiguous)
__global__ void round_w2T_kernel(const float* __restrict__ w2) {
    __shared__ float tile[32][33];
    int k0 = blockIdx.y * 32, nn0 = blockIdx.x * 32;
    int tx = threadIdx.x, ty = threadIdx.y;  // (32,8)
#pragma unroll
    for (int r = 0; r < 4; r++)
        tile[ty + 8 * r][tx] = w2[(size_t)(k0 + ty + 8 * r) * HD + nn0 + tx];
    __syncthreads();
#pragma unroll
    for (int r = 0; r < 4; r++)
        g_w2h[(size_t)(nn0 + ty + 8 * r) * HD + k0 + tx] =
            __float2half_rn(tile[tx][ty + 8 * r]);
}

// ---------------------------------------------------------------------------
// h = relu(edge_attr @ w1 + b1), stored fp16 (A operand).
// ---------------------------------------------------------------------------
__global__ void edge_mlp_kernel(const float* __restrict__ ea,
                                const float* __restrict__ w1,
                                const float* __restrict__ b1) {
    __shared__ float sa[32][20];
    __shared__ float sw[16][128];
    const int e0 = blockIdx.x * 32;
    const int c0 = blockIdx.y * 128;
    const int t  = threadIdx.x;

    if (t < 128) {
        int e = t >> 2, d4 = (t & 3) << 2;
        float4 v = *reinterpret_cast<const float4*>(ea + (e0 + e) * EDIM + d4);
        *reinterpret_cast<float4*>(&sa[e][d4]) = v;
    }
#pragma unroll
    for (int i = 0; i < 2; i++) {
        int id = t + i * 256;
        int d = id >> 5, c4 = (id & 31) << 2;
        float4 v = *reinterpret_cast<const float4*>(w1 + d * HD + c0 + c4);
        *reinterpret_cast<float4*>(&sw[d][c4]) = v;
    }
    __syncthreads();

    const int lc = t & 127;
    const int eh = t >> 7;
    float wreg[16];
#pragma unroll
    for (int d = 0; d < 16; d++) wreg[d] = sw[d][lc];
    const float bias = __ldg(b1 + c0 + lc);

#pragma unroll
    for (int j = 0; j < 16; j++) {
        int e = eh + j * 2;
        float acc = bias;
#pragma unroll
        for (int d = 0; d < 16; d++) acc += sa[e][d] * wreg[d];
        acc = fmaxf(acc, 0.0f);
        g_h[(size_t)(e0 + e) * HD + c0 + lc] = __float2half_rn(acc);
    }
}

// ---------------------------------------------------------------------------
// Fused: theta = g_h @ g_w2h^T + b2 and message scatter into g_agg.
// [M=16384, N=4096, K=4096], FP16 mma m16n8k16, ldmatrix fragments.
// BM=256 BN=128 BK=64, 3-stage cp.async (wait_group 1), 512 thr, 1 CTA/SM.
// Warp grid 4x4 (wm x wn), warp tile 64x32, acc=64 regs/thread, full RF.
// L2 tile traffic: M*N*K*2B*(1/256+1/128) = 6.4 GB/layer (was 8.6).
// Row stride 144 B (16B-aligned; ldmatrix phase banks 36i mod 32 distinct).
// Each warp's 32-col slab maps to ONE input channel i_w=(n0>>6)+(wn>>1):
// epilogue atomicAdds x[src,i_w]*(acc+b2) into g_agg[dst].
// ---------------------------------------------------------------------------
#define BM 256
#define BN 128
#define BK 64
#define ROWB 144                             // bytes per smem row (64 halfs + pad)
#define A_STAGE_B (BM * ROWB)                // 36864 B
#define B_STAGE_B (BN * ROWB)                // 18432 B
#define STAGE_B   (A_STAGE_B + B_STAGE_B)    // 55296 B
#define NSTAGE 3
#define SMEM_BYTES (NSTAGE * STAGE_B)        // 165888 B

__global__ __launch_bounds__(512, 1)
void gemm_fused_kernel(const float* __restrict__ b2,
                       const float* __restrict__ xin,
                       const int* __restrict__ ei) {
    extern __shared__ char smem[];
    const int t  = threadIdx.x;
    const int m0 = blockIdx.y * BM;
    const int n0 = blockIdx.x * BN;
    const int warp = t >> 5, lane = t & 31;
    const int wm = warp >> 2, wn = warp & 3;      // 4x4 warp grid
    const int g = lane >> 2, q = lane & 3;

    const uint32_t sbase = (uint32_t)__cvta_generic_to_shared(smem);

    // ldmatrix per-lane base offsets (bytes within a stage)
    // A x4: M0 rows 0-7 k0-7 | M1 rows 8-15 k0-7 | M2 rows 0-7 k8-15 | M3 rows 8-15 k8-15
    const uint32_t a_lane = (uint32_t)((wm * 64 + (lane & 15)) * ROWB + ((lane >> 4) << 4));
    // B x4: n-rows 0-7 k0-7 | rows 0-7 k8-15 | rows 8-15 k0-7 | rows 8-15 k8-15
    const uint32_t b_lane = (uint32_t)(A_STAGE_B +
        (wn * 32 + ((lane >> 4) << 3) + (lane & 7)) * ROWB + (((lane >> 3) & 1) << 4));

    auto load_tile = [&](int kt) {
        uint32_t base = sbase + (uint32_t)((kt % NSTAGE) * STAGE_B);
#pragma unroll
        for (int i = 0; i < 4; i++) {              // A: 256 rows x 8 x 16B
            int c = t + i * 512;
            int row = c >> 3, ch = c & 7;
            const char* src = (const char*)(g_h + (size_t)(m0 + row) * HD + kt * BK) + ch * 16;
            asm volatile("cp.async.cg.shared.global [%0], [%1], 16;\n"
                :: "r"(base + (uint32_t)(row * ROWB + ch * 16)), "l"(src));
        }
#pragma unroll
        for (int i = 0; i < 2; i++) {              // B: 128 rows x 8 x 16B
            int c = t + i * 512;
            int row = c >> 3, ch = c & 7;
            const char* src = (const char*)(g_w2h + (size_t)(n0 + row) * HD + kt * BK) + ch * 16;
            asm volatile("cp.async.cg.shared.global [%0], [%1], 16;\n"
                :: "r"(base + (uint32_t)(A_STAGE_B + row * ROWB + ch * 16)), "l"(src));
        }
        asm volatile("cp.async.commit_group;\n" ::: "memory");
    };

    float acc[4][4][4];
#pragma unroll
    for (int mt = 0; mt < 4; mt++)
#pragma unroll
        for (int nt = 0; nt < 4; nt++)
#pragma unroll
            for (int r = 0; r < 4; r++) acc[mt][nt][r] = 0.0f;

    const int KT = HD / BK;   // 64
    load_tile(0); load_tile(1);

    for (int kt = 0; kt < KT; kt++) {
        if (kt + 1 < KT)
            asm volatile("cp.async.wait_group 1;\n" ::: "memory");
        else
            asm volatile("cp.async.wait_group 0;\n" ::: "memory");
        __syncthreads();
        if (kt + 2 < KT) load_tile(kt + 2);

        const uint32_t stg = sbase + (uint32_t)((kt % NSTAGE) * STAGE_B);

#pragma unroll
        for (int ks = 0; ks < 4; ks++) {          // four k16 steps per BK=64
            const uint32_t koff = (uint32_t)(ks * 32);   // 16 halfs = 32 B
            uint32_t af[4][4];
#pragma unroll
            for (int mt = 0; mt < 4; mt++) {
                asm volatile(
                    "ldmatrix.sync.aligned.m8n8.x4.shared.b16 {%0,%1,%2,%3}, [%4];\n"
                    : "=r"(af[mt][0]), "=r"(af[mt][1]),
                      "=r"(af[mt][2]), "=r"(af[mt][3])
                    : "r"(stg + a_lane + (uint32_t)(mt * 16 * ROWB) + koff));
            }
            uint32_t bf[4][2];
#pragma unroll
            for (int p = 0; p < 2; p++) {
                asm volatile(
                    "ldmatrix.sync.aligned.m8n8.x4.shared.b16 {%0,%1,%2,%3}, [%4];\n"
                    : "=r"(bf[2 * p][0]), "=r"(bf[2 * p][1]),
                      "=r"(bf[2 * p + 1][0]), "=r"(bf[2 * p + 1][1])
                    : "r"(stg + b_lane + (uint32_t)(p * 16 * ROWB) + koff));
            }
#pragma unroll
            for (int mt = 0; mt < 4; mt++)
#pragma unroll
                for (int nt = 0; nt < 4; nt++) {
                    asm volatile(
                        "mma.sync.aligned.m16n8k16.row.col.f32.f16.f16.f32 "
                        "{%0,%1,%2,%3}, {%4,%5,%6,%7}, {%8,%9}, {%0,%1,%2,%3};\n"
                        : "+f"(acc[mt][nt][0]), "+f"(acc[mt][nt][1]),
                          "+f"(acc[mt][nt][2]), "+f"(acc[mt][nt][3])
                        : "r"(af[mt][0]), "r"(af[mt][1]),
                          "r"(af[mt][2]), "r"(af[mt][3]),
                          "r"(bf[nt][0]), "r"(bf[nt][1]));
                }
        }
    }

    // Fused epilogue: msg contribution for this warp's single input channel,
    // scattered straight into g_agg[dst]. theta = acc + b2.
    const int i_w = (n0 >> 6) + (wn >> 1);
#pragma unroll
    for (int mt = 0; mt < 4; mt++) {
#pragma unroll
        for (int hh = 0; hh < 2; hh++) {
            int e = m0 + wm * 64 + mt * 16 + g + hh * 8;
            int src = __ldg(ei + e);
            int dst = __ldg(ei + N_EDGES + e);
            float xv = __ldg(xin + src * DIM + i_w);
            float* aggp = g_agg + dst * DIM;
#pragma unroll
            for (int nt = 0; nt < 4; nt++) {
                int col = n0 + wn * 32 + nt * 8 + 2 * q;
                int o = col & 63;
                float t0 = acc[mt][nt][2 * hh]     + __ldg(b2 + col);
                float t1 = acc[mt][nt][2 * hh + 1] + __ldg(b2 + col + 1);
                atomicAdd(aggp + o,     xv * t0);
                atomicAdd(aggp + o + 1, xv * t1);
            }
        }
    }
}

// ---------------------------------------------------------------------------
// out[v] = relu(agg[v]/max(cnt,1) + x[v] @ root + bias); one warp per node
// ---------------------------------------------------------------------------
__global__ void node_update_kernel(const float* __restrict__ x,
                                   const float* __restrict__ root,
                                   const float* __restrict__ bias,
                                   float* __restrict__ out) {
    int v = (blockIdx.x * blockDim.x + threadIdx.x) >> 5;
    int lane = threadIdx.x & 31;
    if (v >= N_NODES) return;
    float inv = 1.0f / fmaxf(g_cnt[v], 1.0f);
    float a0 = g_agg[v * DIM + lane] * inv + __ldg(bias + lane);
    float a1 = g_agg[v * DIM + 32 + lane] * inv + __ldg(bias + 32 + lane);
    float xv0 = x[v * DIM + lane];
    float xv1 = x[v * DIM + 32 + lane];
#pragma unroll 8
    for (int i = 0; i < 32; i++) {
        float xi = __shfl_sync(0xffffffffu, xv0, i);
        a0 += xi * __ldg(root + i * 64 + lane);
        a1 += xi * __ldg(root + i * 64 + 32 + lane);
    }
#pragma unroll 8
    for (int i = 0; i < 32; i++) {
        float xi = __shfl_sync(0xffffffffu, xv1, i);
        a0 += xi * __ldg(root + (32 + i) * 64 + lane);
        a1 += xi * __ldg(root + (32 + i) * 64 + 32 + lane);
    }
    out[v * DIM + lane] = fmaxf(a0, 0.0f);
    out[v * DIM + 32 + lane] = fmaxf(a1, 0.0f);
}

// ---------------------------------------------------------------------------
// Global mean pool
// ---------------------------------------------------------------------------
__global__ void pool_sum_kernel(const float* __restrict__ y,
                                const int* __restrict__ batch,
                                float* __restrict__ out) {
    int v = (blockIdx.x * blockDim.x + threadIdx.x) >> 5;
    int lane = threadIdx.x & 31;
    if (v >= N_NODES) return;
    int gr = batch[v];
    atomicAdd(&out[gr * DIM + lane], y[v * DIM + lane]);
    atomicAdd(&out[gr * DIM + 32 + lane], y[v * DIM + 32 + lane]);
    if (lane == 0) atomicAdd(&g_gcnt[gr], 1.0f);
}

__global__ void pool_div_kernel(float* __restrict__ out) {
    int i = blockIdx.x * blockDim.x + threadIdx.x;
    if (i < N_GRAPHS * DIM) out[i] /= fmaxf(g_gcnt[i / DIM], 1.0f);
}

// ---------------------------------------------------------------------------
// Launch
// ---------------------------------------------------------------------------
extern "C" void kernel_launch(void* const* d_in, const int* in_sizes, int n_in,
                              void* d_out, int out_size) {
    (void)in_sizes; (void)n_in; (void)out_size;
    const float* x     = (const float*)d_in[0];
    const int*   ei    = (const int*)d_in[1];
    const float* ea    = (const float*)d_in[2];
    const int*   batch = (const int*)d_in[3];
    const float* W[3][6];
    for (int l = 0; l < 3; l++)
        for (int j = 0; j < 6; j++)
            W[l][j] = (const float*)d_in[4 + l * 6 + j];   // w1,b1,w2,b2,root,bias
    float* out = (float*)d_out;

    cudaFuncSetAttribute(gemm_fused_kernel,
                         cudaFuncAttributeMaxDynamicSharedMemorySize, SMEM_BYTES);

    float *p_cnt, *p_agg, *p_feat, *p_gcnt;
    cudaGetSymbolAddress((void**)&p_cnt,  g_cnt);
    cudaGetSymbolAddress((void**)&p_agg,  g_agg);
    cudaGetSymbolAddress((void**)&p_feat, g_feat);
    cudaGetSymbolAddress((void**)&p_gcnt, g_gcnt);

    zero_kernel<<<(N_NODES + 255) / 256, 256>>>(p_cnt, N_NODES);
    cnt_kernel<<<(N_EDGES + 255) / 256, 256>>>(ei);

    const float* xin = x;
    for (int l = 0; l < 3; l++) {
        float* xout = p_feat + (l & 1) * (N_NODES * DIM);

        dim3 gmlp(N_EDGES / 32, HD / 128);
        edge_mlp_kernel<<<gmlp, 256>>>(ea, W[l][0], W[l][1]);

        round_w2T_kernel<<<dim3(HD / 32, HD / 32), dim3(32, 8)>>>(W[l][2]);

        zero_kernel<<<(N_NODES * DIM + 255) / 256, 256>>>(p_agg, N_NODES * DIM);

        dim3 gg(HD / BN, N_EDGES / BM);   // (32, 64)
        gemm_fused_kernel<<<gg, 512, SMEM_BYTES>>>(W[l][3], xin, ei);

        node_update_kernel<<<N_NODES / 8, 256>>>(xin, W[l][4], W[l][5], xout);
        xin = xout;
    }

    zero_kernel<<<(N_GRAPHS * DIM + 255) / 256, 256>>>(out, N_GRAPHS * DIM);
    zero_kernel<<<1, 256>>>(p_gcnt, N_GRAPHS);
    pool_sum_kernel<<<N_NODES / 8, 256>>>(xin, batch, out);
    pool_div_kernel<<<(N_GRAPHS * DIM + 255) / 256, 256>>>(out);
}

// round 17
// speedup vs baseline: 1.1254x; 1.1254x over previous
#include <cuda_runtime.h>
#include <cuda_fp16.h>
#include <cstdint>

#define N_NODES  4096
#define N_EDGES  16384
#define N_GRAPHS 128
#define DIM      64     // IN = H = 64 for all layers
#define EDIM     16
#define HD       4096   // DIM*DIM, edge-MLP width

// ---------------------------------------------------------------------------
// Scratch (static __device__ globals: no allocation anywhere)
// ---------------------------------------------------------------------------
__device__ __half g_h[N_EDGES * HD];      // 134 MB: relu(ea@w1+b1) in fp16
__device__ __half g_w2h[3][HD * HD];      // 96 MB: per-layer w2^T [N,K] fp16
__device__ float  g_feat[2][N_NODES * DIM];
__device__ float  g_agg[N_NODES * DIM];
__device__ float  g_cnt[N_NODES];
__device__ float  g_gcnt[N_GRAPHS];

// ---------------------------------------------------------------------------
// Utility kernels
// ---------------------------------------------------------------------------
__global__ void zero_kernel(float* __restrict__ p, int n) {
    int i = blockIdx.x * blockDim.x + threadIdx.x;
    if (i < n) p[i] = 0.0f;
}

__global__ void cnt_kernel(const int* __restrict__ ei) {
    int e = blockIdx.x * blockDim.x + threadIdx.x;
    if (e < N_EDGES) atomicAdd(&g_cnt[ei[N_EDGES + e]], 1.0f);
}

// w2 [K,N] fp32 -> g_w2h[l] [N,K] fp16, all 3 layers in one launch (grid.z=l)
__global__ void round_w2T_all_kernel(const float* __restrict__ w2_0,
                                     const float* __restrict__ w2_1,
                                     const float* __restrict__ w2_2) {
    __shared__ float tile[32][33];
    const float* w2 = (blockIdx.z == 0) ? w2_0 : (blockIdx.z == 1) ? w2_1 : w2_2;
    __half* dst = g_w2h[blockIdx.z];
    int k0 = blockIdx.y * 32, nn0 = blockIdx.x * 32;
    int tx = threadIdx.x, ty = threadIdx.y;  // (32,8)
#pragma unroll
    for (int r = 0; r < 4; r++)
        tile[ty + 8 * r][tx] = w2[(size_t)(k0 + ty + 8 * r) * HD + nn0 + tx];
    __syncthreads();
#pragma unroll
    for (int r = 0; r < 4; r++)
        dst[(size_t)(nn0 + ty + 8 * r) * HD + k0 + tx] =
            __float2half_rn(tile[tx][ty + 8 * r]);
}

// ---------------------------------------------------------------------------
// h = relu(edge_attr @ w1 + b1), stored fp16 (A operand).
// v2: tile 64 edges x 256 cols, 256 threads, each thread owns a column PAIR
// and 32 edges. Halves w1 L2 traffic (16 KB slab per 64 edges) and stores
// __half2 (warp writes a full 128 B line).
// ---------------------------------------------------------------------------
__global__ void edge_mlp_kernel(const float* __restrict__ ea,
                                const float* __restrict__ w1,
                                const float* __restrict__ b1) {
    __shared__ float sa[64][20];     // 64 edges x 16 attrs (padded row 80 B)
    __shared__ float sw[16][256];    // w1 slab: 16 attrs x 256 cols
    const int e0 = blockIdx.x * 64;
    const int c0 = blockIdx.y * 256;
    const int t  = threadIdx.x;

    {   // sa: 64 x 16 floats = 256 float4, one per thread
        int e = t >> 2, d4 = (t & 3) << 2;
        float4 v = *reinterpret_cast<const float4*>(ea + (e0 + e) * EDIM + d4);
        *reinterpret_cast<float4*>(&sa[e][d4]) = v;
    }
#pragma unroll
    for (int i = 0; i < 4; i++) {    // sw: 16 x 256 floats = 1024 float4
        int id = t + i * 256;
        int d = id >> 6, c4 = (id & 63) << 2;
        float4 v = *reinterpret_cast<const float4*>(w1 + d * HD + c0 + c4);
        *reinterpret_cast<float4*>(&sw[d][c4]) = v;
    }
    __syncthreads();

    const int pc = t & 127;          // column-pair index: cols 2*pc, 2*pc+1
    const int eh = t >> 7;           // 0/1 edge phase
    float wr0[16], wr1[16];
#pragma unroll
    for (int d = 0; d < 16; d++) { wr0[d] = sw[d][2 * pc]; wr1[d] = sw[d][2 * pc + 1]; }
    const float bias0 = __ldg(b1 + c0 + 2 * pc);
    const float bias1 = __ldg(b1 + c0 + 2 * pc + 1);

#pragma unroll
    for (int j = 0; j < 32; j++) {
        int e = eh + j * 2;
        float a0 = bias0, a1 = bias1;
#pragma unroll
        for (int d = 0; d < 16; d++) {
            float av = sa[e][d];
            a0 += av * wr0[d];
            a1 += av * wr1[d];
        }
        __half2 hv = __floats2half2_rn(fmaxf(a0, 0.0f), fmaxf(a1, 0.0f));
        *reinterpret_cast<__half2*>(g_h + (size_t)(e0 + e) * HD + c0 + 2 * pc) = hv;
    }
}

// ---------------------------------------------------------------------------
// Fused: theta = g_h @ g_w2h[l]^T + b2 and message scatter into g_agg.
// [M=16384, N=4096, K=4096], FP16 mma m16n8k16, ldmatrix fragments.
// BM=128 BN=128 BK=64, 2-stage cp.async, 256 thr, 2 CTAs/SM (R14 config —
// proven local optimum; bigger tiles spill). Row stride 144 B.
// Each warp's 32-col slab maps to ONE input channel i_w=(n0>>6)+(wn>>1):
// epilogue atomicAdds x[src,i_w]*(acc+b2) into g_agg[dst].
// ---------------------------------------------------------------------------
#define BM 128
#define BN 128
#define BK 64
#define ROWB 144                             // bytes per smem row (64 halfs + pad)
#define A_STAGE_B (BM * ROWB)                // 18432 B
#define B_STAGE_B (BN * ROWB)                // 18432 B
#define STAGE_B   (A_STAGE_B + B_STAGE_B)    // 36864 B
#define NSTAGE 2
#define SMEM_BYTES (NSTAGE * STAGE_B)        // 73728 B

__global__ __launch_bounds__(256, 2)
void gemm_fused_kernel(const __half* __restrict__ w2h,
                       const float* __restrict__ b2,
                       const float* __restrict__ xin,
                       const int* __restrict__ ei) {
    extern __shared__ char smem[];
    const int t  = threadIdx.x;
    const int m0 = blockIdx.y * BM;
    const int n0 = blockIdx.x * BN;
    const int warp = t >> 5, lane = t & 31;
    const int wm = warp >> 2, wn = warp & 3;      // 2x4 warp grid
    const int g = lane >> 2, q = lane & 3;

    const uint32_t sbase = (uint32_t)__cvta_generic_to_shared(smem);

    // ldmatrix per-lane base offsets (bytes within a stage)
    const uint32_t a_lane = (uint32_t)((wm * 64 + (lane & 15)) * ROWB + ((lane >> 4) << 4));
    const uint32_t b_lane = (uint32_t)(A_STAGE_B +
        (wn * 32 + ((lane >> 4) << 3) + (lane & 7)) * ROWB + (((lane >> 3) & 1) << 4));

    auto load_tile = [&](int kt) {
        uint32_t base = sbase + (uint32_t)((kt & 1) * STAGE_B);
#pragma unroll
        for (int i = 0; i < 4; i++) {              // A: 128 rows x 8 x 16B
            int c = t + i * 256;
            int row = c >> 3, ch = c & 7;
            const char* src = (const char*)(g_h + (size_t)(m0 + row) * HD + kt * BK) + ch * 16;
            asm volatile("cp.async.cg.shared.global [%0], [%1], 16;\n"
                :: "r"(base + (uint32_t)(row * ROWB + ch * 16)), "l"(src));
        }
#pragma unroll
        for (int i = 0; i < 4; i++) {              // B: 128 rows x 8 x 16B
            int c = t + i * 256;
            int row = c >> 3, ch = c & 7;
            const char* src = (const char*)(w2h + (size_t)(n0 + row) * HD + kt * BK) + ch * 16;
            asm volatile("cp.async.cg.shared.global [%0], [%1], 16;\n"
                :: "r"(base + (uint32_t)(A_STAGE_B + row * ROWB + ch * 16)), "l"(src));
        }
        asm volatile("cp.async.commit_group;\n" ::: "memory");
    };

    float acc[4][4][4];
#pragma unroll
    for (int mt = 0; mt < 4; mt++)
#pragma unroll
        for (int nt = 0; nt < 4; nt++)
#pragma unroll
            for (int r = 0; r < 4; r++) acc[mt][nt][r] = 0.0f;

    const int KT = HD / BK;   // 64
    load_tile(0);

    for (int kt = 0; kt < KT; kt++) {
        asm volatile("cp.async.wait_group 0;\n" ::: "memory");
        __syncthreads();
        if (kt + 1 < KT) load_tile(kt + 1);

        const uint32_t stg = sbase + (uint32_t)((kt & 1) * STAGE_B);

#pragma unroll
        for (int ks = 0; ks < 4; ks++) {          // four k16 steps per BK=64
            const uint32_t koff = (uint32_t)(ks * 32);   // 16 halfs = 32 B
            uint32_t af[4][4];
#pragma unroll
            for (int mt = 0; mt < 4; mt++) {
                asm volatile(
                    "ldmatrix.sync.aligned.m8n8.x4.shared.b16 {%0,%1,%2,%3}, [%4];\n"
                    : "=r"(af[mt][0]), "=r"(af[mt][1]),
                      "=r"(af[mt][2]), "=r"(af[mt][3])
                    : "r"(stg + a_lane + (uint32_t)(mt * 16 * ROWB) + koff));
            }
            uint32_t bf[4][2];
#pragma unroll
            for (int p = 0; p < 2; p++) {
                asm volatile(
                    "ldmatrix.sync.aligned.m8n8.x4.shared.b16 {%0,%1,%2,%3}, [%4];\n"
                    : "=r"(bf[2 * p][0]), "=r"(bf[2 * p][1]),
                      "=r"(bf[2 * p + 1][0]), "=r"(bf[2 * p + 1][1])
                    : "r"(stg + b_lane + (uint32_t)(p * 16 * ROWB) + koff));
            }
#pragma unroll
            for (int mt = 0; mt < 4; mt++)
#pragma unroll
                for (int nt = 0; nt < 4; nt++) {
                    asm volatile(
                        "mma.sync.aligned.m16n8k16.row.col.f32.f16.f16.f32 "
                        "{%0,%1,%2,%3}, {%4,%5,%6,%7}, {%8,%9}, {%0,%1,%2,%3};\n"
                        : "+f"(acc[mt][nt][0]), "+f"(acc[mt][nt][1]),
                          "+f"(acc[mt][nt][2]), "+f"(acc[mt][nt][3])
                        : "r"(af[mt][0]), "r"(af[mt][1]),
                          "r"(af[mt][2]), "r"(af[mt][3]),
                          "r"(bf[nt][0]), "r"(bf[nt][1]));
                }
        }
    }

    // Fused epilogue: msg contribution for this warp's single input channel,
    // scattered straight into g_agg[dst]. theta = acc + b2.
    const int i_w = (n0 >> 6) + (wn >> 1);
#pragma unroll
    for (int mt = 0; mt < 4; mt++) {
#pragma unroll
        for (int hh = 0; hh < 2; hh++) {
            int e = m0 + wm * 64 + mt * 16 + g + hh * 8;
            int src = __ldg(ei + e);
            int dst = __ldg(ei + N_EDGES + e);
            float xv = __ldg(xin + src * DIM + i_w);
            float* aggp = g_agg + dst * DIM;
#pragma unroll
            for (int nt = 0; nt < 4; nt++) {
                int col = n0 + wn * 32 + nt * 8 + 2 * q;
                int o = col & 63;
                float t0 = acc[mt][nt][2 * hh]     + __ldg(b2 + col);
                float t1 = acc[mt][nt][2 * hh + 1] + __ldg(b2 + col + 1);
                atomicAdd(aggp + o,     xv * t0);
                atomicAdd(aggp + o + 1, xv * t1);
            }
        }
    }
}

// ---------------------------------------------------------------------------
// out[v] = relu(agg[v]/max(cnt,1) + x[v] @ root + bias); one warp per node
// ---------------------------------------------------------------------------
__global__ void node_update_kernel(const float* __restrict__ x,
                                   const float* __restrict__ root,
                                   const float* __restrict__ bias,
                                   float* __restrict__ out) {
    int v = (blockIdx.x * blockDim.x + threadIdx.x) >> 5;
    int lane = threadIdx.x & 31;
    if (v >= N_NODES) return;
    float inv = 1.0f / fmaxf(g_cnt[v], 1.0f);
    float a0 = g_agg[v * DIM + lane] * inv + __ldg(bias + lane);
    float a1 = g_agg[v * DIM + 32 + lane] * inv + __ldg(bias + 32 + lane);
    float xv0 = x[v * DIM + lane];
    float xv1 = x[v * DIM + 32 + lane];
#pragma unroll 8
    for (int i = 0; i < 32; i++) {
        float xi = __shfl_sync(0xffffffffu, xv0, i);
        a0 += xi * __ldg(root + i * 64 + lane);
        a1 += xi * __ldg(root + i * 64 + 32 + lane);
    }
#pragma unroll 8
    for (int i = 0; i < 32; i++) {
        float xi = __shfl_sync(0xffffffffu, xv1, i);
        a0 += xi * __ldg(root + (32 + i) * 64 + lane);
        a1 += xi * __ldg(root + (32 + i) * 64 + 32 + lane);
    }
    out[v * DIM + lane] = fmaxf(a0, 0.0f);
    out[v * DIM + 32 + lane] = fmaxf(a1, 0.0f);
}

// ---------------------------------------------------------------------------
// Global mean pool
// ---------------------------------------------------------------------------
__global__ void pool_sum_kernel(const float* __restrict__ y,
                                const int* __restrict__ batch,
                                float* __restrict__ out) {
    int v = (blockIdx.x * blockDim.x + threadIdx.x) >> 5;
    int lane = threadIdx.x & 31;
    if (v >= N_NODES) return;
    int gr = batch[v];
    atomicAdd(&out[gr * DIM + lane], y[v * DIM + lane]);
    atomicAdd(&out[gr * DIM + 32 + lane], y[v * DIM + 32 + lane]);
    if (lane == 0) atomicAdd(&g_gcnt[gr], 1.0f);
}

__global__ void pool_div_kernel(float* __restrict__ out) {
    int i = blockIdx.x * blockDim.x + threadIdx.x;
    if (i < N_GRAPHS * DIM) out[i] /= fmaxf(g_gcnt[i / DIM], 1.0f);
}

// ---------------------------------------------------------------------------
// Launch
// ---------------------------------------------------------------------------
extern "C" void kernel_launch(void* const* d_in, const int* in_sizes, int n_in,
                              void* d_out, int out_size) {
    (void)in_sizes; (void)n_in; (void)out_size;
    const float* x     = (const float*)d_in[0];
    const int*   ei    = (const int*)d_in[1];
    const float* ea    = (const float*)d_in[2];
    const int*   batch = (const int*)d_in[3];
    const float* W[3][6];
    for (int l = 0; l < 3; l++)
        for (int j = 0; j < 6; j++)
            W[l][j] = (const float*)d_in[4 + l * 6 + j];   // w1,b1,w2,b2,root,bias
    float* out = (float*)d_out;

    cudaFuncSetAttribute(gemm_fused_kernel,
                         cudaFuncAttributeMaxDynamicSharedMemorySize, SMEM_BYTES);

    float *p_cnt, *p_agg, *p_feat, *p_gcnt;
    __half* p_w2h;
    cudaGetSymbolAddress((void**)&p_cnt,  g_cnt);
    cudaGetSymbolAddress((void**)&p_agg,  g_agg);
    cudaGetSymbolAddress((void**)&p_feat, g_feat);
    cudaGetSymbolAddress((void**)&p_gcnt, g_gcnt);
    cudaGetSymbolAddress((void**)&p_w2h,  g_w2h);

    zero_kernel<<<(N_NODES + 255) / 256, 256>>>(p_cnt, N_NODES);
    cnt_kernel<<<(N_EDGES + 255) / 256, 256>>>(ei);

    // All 3 layers' w2 -> fp16 [N,K] upfront, one launch
    round_w2T_all_kernel<<<dim3(HD / 32, HD / 32, 3), dim3(32, 8)>>>(
        W[0][2], W[1][2], W[2][2]);

    const float* xin = x;
    for (int l = 0; l < 3; l++) {
        float* xout = p_feat + (l & 1) * (N_NODES * DIM);

        dim3 gmlp(N_EDGES / 64, HD / 256);   // (256, 16)
        edge_mlp_kernel<<<gmlp, 256>>>(ea, W[l][0], W[l][1]);

        zero_kernel<<<(N_NODES * DIM + 255) / 256, 256>>>(p_agg, N_NODES * DIM);

        dim3 gg(HD / BN, N_EDGES / BM);   // (32, 128)
        gemm_fused_kernel<<<gg, 256, SMEM_BYTES>>>(
            p_w2h + (size_t)l * HD * HD, W[l][3], xin, ei);

        node_update_kernel<<<N_NODES / 8, 256>>>(xin, W[l][4], W[l][5], xout);
        xin = xout;
    }

    zero_kernel<<<(N_GRAPHS * DIM + 255) / 256, 256>>>(out, N_GRAPHS * DIM);
    zero_kernel<<<1, 256>>>(p_gcnt, N_GRAPHS);
    pool_sum_kernel<<<N_NODES / 8, 256>>>(xin, batch, out);
    pool_div_kernel<<<(N_GRAPHS * DIM + 255) / 256, 256>>>(out);
}